// round 2
// baseline (speedup 1.0000x reference)
#include <cuda_runtime.h>
#include <cstdint>
#include <math.h>

#define Bn 64
#define Sn 512
#define Dn 768
#define BSn (Bn * Sn)

#define PAD_ID 0
#define SEP_ID 103
#define IGNORE_ID 100

// Scratch (no cudaMalloc allowed)
__device__ float g_em[BSn * 2];   // emissions (B,S,2)
__device__ float g_llh[Bn];       // per-batch log-likelihood

// ---------------------------------------------------------------------------
// Kernel 1: em = relu((seq * mask) @ W^T + b); also emit labels_m and mask.
// 8 warps per block, one token per warp. Coalesced float4 loads.
// ---------------------------------------------------------------------------
__global__ __launch_bounds__(256) void emissions_kernel(
    const float* __restrict__ seq,
    const int* __restrict__ ids,
    const int* __restrict__ labels,
    const float* __restrict__ W,
    const float* __restrict__ bvec,
    float* __restrict__ out,
    int out_size)
{
    __shared__ float4 sW0[Dn / 4];
    __shared__ float4 sW1[Dn / 4];

    int tid = threadIdx.x;
    for (int i = tid; i < Dn / 4; i += blockDim.x) {
        sW0[i] = reinterpret_cast<const float4*>(W)[i];
        sW1[i] = reinterpret_cast<const float4*>(W + Dn)[i];
    }
    __syncthreads();

    int warp = tid >> 5;
    int lane = tid & 31;
    int token = blockIdx.x * 8 + warp;  // 4096 blocks * 8 = 32768

    const float4* row = reinterpret_cast<const float4*>(seq + (size_t)token * Dn);
    float s0 = 0.f, s1 = 0.f;
#pragma unroll
    for (int k = 0; k < 6; k++) {
        int idx = lane + k * 32;
        float4 x  = row[idx];
        float4 w0 = sW0[idx];
        float4 w1 = sW1[idx];
        s0 += x.x * w0.x + x.y * w0.y + x.z * w0.z + x.w * w0.w;
        s1 += x.x * w1.x + x.y * w1.y + x.z * w1.z + x.w * w1.w;
    }
#pragma unroll
    for (int off = 16; off; off >>= 1) {
        s0 += __shfl_down_sync(0xFFFFFFFFu, s0, off);
        s1 += __shfl_down_sync(0xFFFFFFFFu, s1, off);
    }

    if (lane == 0) {
        int id  = ids[token];
        int lab = labels[token];
        bool m = (id != PAD_ID) && (id != SEP_ID) && (lab != IGNORE_ID);
        float dot0 = m ? s0 : 0.f;
        float dot1 = m ? s1 : 0.f;
        float e0 = fmaxf(dot0 + bvec[0], 0.f);
        float e1 = fmaxf(dot1 + bvec[1], 0.f);
        g_em[token * 2 + 0] = e0;
        g_em[token * 2 + 1] = e1;
        if (out_size >= 1 + 3 * BSn) {
            out[1 + BSn + token]     = m ? (float)lab : 0.f;  // labels_m
            out[1 + 2 * BSn + token] = m ? 1.f : 0.f;         // mask
        }
    }
}

// ---------------------------------------------------------------------------
// CRF kernel: one block per batch.
// Warps 0-7 (256 thr): gold score reduction + logZ via associative lse 2x2
// matrix tree reduction (named barrier 1, 256 threads).
// Warp 8, lane 0: serial Viterbi forward + backtrack (concurrent with tree).
// ---------------------------------------------------------------------------
__device__ __forceinline__ float lse2(float a, float b) {
    float m = fmaxf(a, b);
    if (m == -INFINITY) return -INFINITY;
    float n = fminf(a, b);
    return m + log1pf(expf(n - m));
}

// 2x2 log-semiring matmul; float4 layout: x=m00 y=m01 z=m10 w=m11
__device__ __forceinline__ float4 lsemm(float4 A, float4 B) {
    float4 C;
    C.x = lse2(A.x + B.x, A.y + B.z);
    C.y = lse2(A.x + B.y, A.y + B.w);
    C.z = lse2(A.z + B.x, A.w + B.z);
    C.w = lse2(A.z + B.y, A.w + B.w);
    return C;
}

#define BAR256() asm volatile("bar.sync 1, 256;" ::: "memory")

__global__ __launch_bounds__(288) void crf_kernel(
    const int* __restrict__ ids,
    const int* __restrict__ labels,
    const float* __restrict__ startt,
    const float* __restrict__ endt,
    const float* __restrict__ trans,
    float* __restrict__ out,
    int out_size)
{
    __shared__ float  sem[Sn][2];    // emissions
    __shared__ int    stag[Sn];      // gold tags (labels_m)
    __shared__ float4 smat[256];     // tree buffer
    __shared__ float  sred[256];     // gold-score reduction
    __shared__ float  svit[Sn][2];   // viterbi forward scores
    __shared__ int    souttag[Sn];   // decoded path

    const int b   = blockIdx.x;
    const int tid = threadIdx.x;

    // ---- load emissions + tags ----
    const float* emrow = g_em + (size_t)b * Sn * 2;
    for (int i = tid; i < Sn * 2; i += 288)
        reinterpret_cast<float*>(sem)[i] = emrow[i];
    for (int s = tid; s < Sn; s += 288) {
        int id  = ids[(size_t)b * Sn + s];
        int lab = labels[(size_t)b * Sn + s];
        bool m = (id != PAD_ID) && (id != SEP_ID) && (lab != IGNORE_ID);
        stag[s] = m ? lab : 0;
    }
    __syncthreads();

    const float t00 = trans[0], t01 = trans[1], t10 = trans[2], t11 = trans[3];

    if (tid < 256) {
        // ---- gold score partial ----
        float part = 0.f;
        for (int s = tid; s < Sn; s += 256) {
            int a = stag[s];
            part += sem[s][a];
            if (s < Sn - 1) {
                int c = stag[s + 1];
                part += (a == 0) ? (c == 0 ? t00 : t01) : (c == 0 ? t10 : t11);
            }
        }
        sred[tid] = part;

        // ---- logZ leaves: M_t[i][j] = trans[i][j] + em[t][j], t = 1..511 ----
        // thread tid covers leaves t = 2*tid+1, 2*tid+2
        int t0 = 2 * tid + 1;   // always valid (<= 511)
        float4 Mv;
        {
            float e0 = sem[t0][0], e1 = sem[t0][1];
            Mv.x = t00 + e0; Mv.y = t01 + e1;
            Mv.z = t10 + e0; Mv.w = t11 + e1;
        }
        int t1 = 2 * tid + 2;
        if (t1 <= Sn - 1) {
            float4 Mb;
            float e0 = sem[t1][0], e1 = sem[t1][1];
            Mb.x = t00 + e0; Mb.y = t01 + e1;
            Mb.z = t10 + e0; Mb.w = t11 + e1;
            Mv = lsemm(Mv, Mb);
        }
        smat[tid] = Mv;
        BAR256();

        // ---- ordered tree reduction (non-commutative, adjacent pairing) ----
        for (int n = 128; n >= 1; n >>= 1) {
            float4 a4, b4;
            bool act = (tid < n);
            if (act) { a4 = smat[2 * tid]; b4 = smat[2 * tid + 1]; }
            BAR256();
            if (act) smat[tid] = lsemm(a4, b4);
            BAR256();
        }

        // ---- gold score reduction ----
        for (int n = 128; n >= 1; n >>= 1) {
            if (tid < n) sred[tid] += sred[tid + n];
            BAR256();
        }

        if (tid == 0) {
            float score = sred[0] + startt[stag[0]] + endt[stag[Sn - 1]];
            float a0 = startt[0] + sem[0][0];
            float a1 = startt[1] + sem[0][1];
            float4 M = smat[0];
            float f0 = lse2(a0 + M.x, a1 + M.z);
            float f1 = lse2(a0 + M.y, a1 + M.w);
            float logZ = lse2(f0 + endt[0], f1 + endt[1]);
            g_llh[b] = score - logZ;
        }
    } else if (tid == 256) {
        // ---- Viterbi forward (serial, dedicated warp) ----
        float v0 = startt[0] + sem[0][0];
        float v1 = startt[1] + sem[0][1];
        svit[0][0] = v0; svit[0][1] = v1;
#pragma unroll 4
        for (int t = 1; t < Sn; t++) {
            float n0 = fmaxf(v0 + t00, v1 + t10) + sem[t][0];
            float n1 = fmaxf(v0 + t01, v1 + t11) + sem[t][1];
            svit[t][0] = n0; svit[t][1] = n1;
            v0 = n0; v1 = n1;
        }
        float f0 = v0 + endt[0];
        float f1 = v1 + endt[1];
        int tag = (f1 > f0) ? 1 : 0;   // argmax, lowest index on tie
        souttag[Sn - 1] = tag;
        // ---- backtrack ----
#pragma unroll 4
        for (int t = Sn - 1; t >= 1; t--) {
            float p0 = svit[t - 1][0] + (tag ? t01 : t00);
            float p1 = svit[t - 1][1] + (tag ? t11 : t10);
            tag = (p1 > p0) ? 1 : 0;
            souttag[t - 1] = tag;
        }
    }

    __syncthreads();

    // ---- write viterbi path ----
    if (out_size >= 1 + BSn) {
        for (int s = tid; s < Sn; s += 288)
            out[1 + (size_t)b * Sn + s] = (float)souttag[s];
    }
}

// ---------------------------------------------------------------------------
// Kernel 3: loss = sum(llh) / (B*S)
// ---------------------------------------------------------------------------
__global__ void loss_kernel(float* __restrict__ out)
{
    int t = threadIdx.x;   // 64 threads
    double v = (double)g_llh[t];
#pragma unroll
    for (int off = 16; off; off >>= 1)
        v += __shfl_down_sync(0xFFFFFFFFu, v, off);
    __shared__ double sh[2];
    if ((t & 31) == 0) sh[t >> 5] = v;
    __syncthreads();
    if (t == 0)
        out[0] = (float)((sh[0] + sh[1]) / (double)(BSn));
}

// ---------------------------------------------------------------------------
extern "C" void kernel_launch(void* const* d_in, const int* in_sizes, int n_in,
                              void* d_out, int out_size)
{
    const float* seq    = (const float*)d_in[0];
    const int*   ids    = (const int*)d_in[1];
    const int*   labels = (const int*)d_in[2];
    const float* W      = (const float*)d_in[3];
    const float* bvec   = (const float*)d_in[4];
    const float* startt = (const float*)d_in[5];
    const float* endt   = (const float*)d_in[6];
    const float* trans  = (const float*)d_in[7];
    float* out = (float*)d_out;

    emissions_kernel<<<BSn / 8, 256>>>(seq, ids, labels, W, bvec, out, out_size);
    crf_kernel<<<Bn, 288>>>(ids, labels, startt, endt, trans, out, out_size);
    loss_kernel<<<1, 64>>>(out);
}

// round 3
// speedup vs baseline: 1.5528x; 1.5528x over previous
#include <cuda_runtime.h>
#include <cstdint>
#include <math.h>

#define Bn 64
#define Sn 512
#define Dn 768
#define BSn (Bn * Sn)

#define PAD_ID 0
#define SEP_ID 103
#define IGNORE_ID 100

#define NBLK 296              // 2 CTAs per SM on 148 SMs
#define NWARP (NBLK * 8)      // 2368 global warps
#define DEPTH 4               // cp.async ring depth per warp

// Scratch (no cudaMalloc allowed)
__device__ float g_em[BSn * 2];            // emissions (B,S,2)
__device__ unsigned long long g_acc;       // fixed-point llh accumulator
__device__ int g_done;                     // batches finished

// ---------------------------------------------------------------------------
// Kernel 1: em = relu((seq * mask) @ W^T + b); also labels_m and mask outputs.
// Persistent grid, warp-per-token, depth-4 cp.async ring into smem.
// W kept in registers (12 x float4 per thread). No __syncthreads in mainloop.
// ---------------------------------------------------------------------------
__global__ __launch_bounds__(256, 2) void emissions_kernel(
    const float* __restrict__ seq,
    const int* __restrict__ ids,
    const int* __restrict__ labels,
    const float* __restrict__ W,
    const float* __restrict__ bvec,
    float* __restrict__ out,
    int out_size)
{
    extern __shared__ float4 sbuf[];   // [8 warps][DEPTH][192 float4]

    const int tid  = threadIdx.x;
    const int warp = tid >> 5;
    const int lane = tid & 31;

    if (blockIdx.x == 0 && tid == 0) { g_acc = 0ULL; g_done = 0; }

    // W rows in registers (same float4 index lane+32k used for every token)
    float4 w0[6], w1[6];
    const float4* W4 = reinterpret_cast<const float4*>(W);
#pragma unroll
    for (int k = 0; k < 6; k++) {
        w0[k] = W4[lane + 32 * k];
        w1[k] = W4[192 + lane + 32 * k];
    }
    const float b0 = bvec[0];
    const float b1 = bvec[1];

    const int gw   = blockIdx.x * 8 + warp;          // global warp id
    const int ntok = (BSn - gw + NWARP - 1) / NWARP; // 13 or 14 tokens

    // Preload this warp's ids/labels, one token per lane; fetch via shuffle.
    int myid = 0, mylab = 0;
    if (lane < ntok) {
        int t = gw + lane * NWARP;
        myid  = ids[t];
        mylab = labels[t];
    }

    float4* mybuf = sbuf + (size_t)warp * DEPTH * 192;

    auto issue = [&](int i) {
        if (i < ntok) {
            int t = gw + i * NWARP;
            const float4* g = reinterpret_cast<const float4*>(seq + (size_t)t * Dn) + lane;
            uint32_t sm = (uint32_t)__cvta_generic_to_shared(mybuf + (i & (DEPTH - 1)) * 192 + lane);
#pragma unroll
            for (int k = 0; k < 6; k++) {
                asm volatile("cp.async.cg.shared.global [%0], [%1], 16;\n"
                             :: "r"(sm + k * 32 * 16), "l"(g + k * 32) : "memory");
            }
        }
        asm volatile("cp.async.commit_group;\n" ::: "memory");
    };

    issue(0); issue(1); issue(2); issue(3);

    for (int i = 0; i < ntok; i++) {
        asm volatile("cp.async.wait_group 3;\n" ::: "memory");
        const float4* xb = mybuf + (i & (DEPTH - 1)) * 192;

        float s0 = 0.f, s1 = 0.f;
#pragma unroll
        for (int k = 0; k < 6; k++) {
            float4 x = xb[lane + 32 * k];
            s0 += x.x * w0[k].x + x.y * w0[k].y + x.z * w0[k].z + x.w * w0[k].w;
            s1 += x.x * w1[k].x + x.y * w1[k].y + x.z * w1[k].z + x.w * w1[k].w;
        }

        issue(i + 4);   // refill the slot just consumed (lands >>29cyc later)

#pragma unroll
        for (int off = 16; off; off >>= 1) {
            s0 += __shfl_down_sync(0xFFFFFFFFu, s0, off);
            s1 += __shfl_down_sync(0xFFFFFFFFu, s1, off);
        }
        int id_i  = __shfl_sync(0xFFFFFFFFu, myid, i);
        int lab_i = __shfl_sync(0xFFFFFFFFu, mylab, i);

        if (lane == 0) {
            int t = gw + i * NWARP;
            bool m = (id_i != PAD_ID) && (id_i != SEP_ID) && (lab_i != IGNORE_ID);
            float dot0 = m ? s0 : 0.f;
            float dot1 = m ? s1 : 0.f;
            g_em[t * 2 + 0] = fmaxf(dot0 + b0, 0.f);
            g_em[t * 2 + 1] = fmaxf(dot1 + b1, 0.f);
            if (out_size >= 1 + 3 * BSn) {
                out[1 + BSn + t]     = m ? (float)lab_i : 0.f;  // labels_m
                out[1 + 2 * BSn + t] = m ? 1.f : 0.f;           // mask
            }
        }
    }
}

// ---------------------------------------------------------------------------
// CRF kernel: one block (288 thr) per batch.
// Warps 0-7: gold score + logZ lse 2x2 matrix tree (named barrier, 256 thr).
// Warp 8 lane 0: serial Viterbi FORWARD only (concurrent with tree).
// Then all: backtrack as exact integer map-composition suffix scan (9 steps).
// Loss folded in via fixed-point atomic; last batch writes out[0].
// ---------------------------------------------------------------------------
__device__ __forceinline__ float lse2(float a, float b) {
    float m = fmaxf(a, b);
    if (m == -INFINITY) return -INFINITY;
    float n = fminf(a, b);
    return m + log1pf(expf(n - m));
}

__device__ __forceinline__ float4 lsemm(float4 A, float4 B) {
    float4 C;
    C.x = lse2(A.x + B.x, A.y + B.z);
    C.y = lse2(A.x + B.y, A.y + B.w);
    C.z = lse2(A.z + B.x, A.w + B.z);
    C.w = lse2(A.z + B.y, A.w + B.w);
    return C;
}

// compose maps: (f o g)(x) = f(g(x)); maps encoded as 2 bits (bit x = f(x))
__device__ __forceinline__ int mapcomp(int f, int g) {
    int h0 = (f >> (g & 1)) & 1;
    int h1 = (f >> ((g >> 1) & 1)) & 1;
    return h0 | (h1 << 1);
}

#define BAR256() asm volatile("bar.sync 1, 256;" ::: "memory")

__global__ __launch_bounds__(288) void crf_kernel(
    const int* __restrict__ ids,
    const int* __restrict__ labels,
    const float* __restrict__ startt,
    const float* __restrict__ endt,
    const float* __restrict__ trans,
    float* __restrict__ out,
    int out_size)
{
    __shared__ float  sem[Sn][2];
    __shared__ int    stag[Sn];
    __shared__ float4 smat[256];
    __shared__ float  sred[256];
    __shared__ float  svit[Sn][2];
    __shared__ int    sA[Sn];
    __shared__ int    sB[Sn];
    __shared__ int    slast;

    const int b   = blockIdx.x;
    const int tid = threadIdx.x;

    const float* emrow = g_em + (size_t)b * Sn * 2;
    for (int i = tid; i < Sn * 2; i += 288)
        reinterpret_cast<float*>(sem)[i] = emrow[i];
    for (int s = tid; s < Sn; s += 288) {
        int id  = ids[(size_t)b * Sn + s];
        int lab = labels[(size_t)b * Sn + s];
        bool m = (id != PAD_ID) && (id != SEP_ID) && (lab != IGNORE_ID);
        stag[s] = m ? lab : 0;
    }
    __syncthreads();

    const float t00 = trans[0], t01 = trans[1], t10 = trans[2], t11 = trans[3];

    if (tid < 256) {
        // gold score partial
        float part = 0.f;
        for (int s = tid; s < Sn; s += 256) {
            int a = stag[s];
            part += sem[s][a];
            if (s < Sn - 1) {
                int c = stag[s + 1];
                part += (a == 0) ? (c == 0 ? t00 : t01) : (c == 0 ? t10 : t11);
            }
        }
        sred[tid] = part;

        // logZ leaves (t = 2*tid+1, 2*tid+2)
        int t0 = 2 * tid + 1;
        float4 Mv;
        {
            float e0 = sem[t0][0], e1 = sem[t0][1];
            Mv.x = t00 + e0; Mv.y = t01 + e1;
            Mv.z = t10 + e0; Mv.w = t11 + e1;
        }
        int t1 = 2 * tid + 2;
        if (t1 <= Sn - 1) {
            float4 Mb;
            float e0 = sem[t1][0], e1 = sem[t1][1];
            Mb.x = t00 + e0; Mb.y = t01 + e1;
            Mb.z = t10 + e0; Mb.w = t11 + e1;
            Mv = lsemm(Mv, Mb);
        }
        smat[tid] = Mv;
        BAR256();

        for (int n = 128; n >= 1; n >>= 1) {
            float4 a4, b4;
            bool act = (tid < n);
            if (act) { a4 = smat[2 * tid]; b4 = smat[2 * tid + 1]; }
            BAR256();
            if (act) smat[tid] = lsemm(a4, b4);
            BAR256();
        }
        for (int n = 128; n >= 1; n >>= 1) {
            if (tid < n) sred[tid] += sred[tid + n];
            BAR256();
        }

        if (tid == 0) {
            float score = sred[0] + startt[stag[0]] + endt[stag[Sn - 1]];
            float a0 = startt[0] + sem[0][0];
            float a1 = startt[1] + sem[0][1];
            float4 M = smat[0];
            float f0 = lse2(a0 + M.x, a1 + M.z);
            float f1 = lse2(a0 + M.y, a1 + M.w);
            float logZ = lse2(f0 + endt[0], f1 + endt[1]);
            float llh = score - logZ;
            long long fx = __double2ll_rn((double)llh * 4294967296.0);
            atomicAdd(&g_acc, (unsigned long long)fx);
            __threadfence();
            int old = atomicAdd(&g_done, 1);
            if (old == Bn - 1) {
                __threadfence();
                unsigned long long a = atomicAdd(&g_acc, 0ULL);
                double s = (double)(long long)a * (1.0 / 4294967296.0);
                out[0] = (float)(s / (double)BSn);
            }
        }
    } else if (tid == 256) {
        // serial Viterbi forward (exact R2 numerics)
        float v0 = startt[0] + sem[0][0];
        float v1 = startt[1] + sem[0][1];
        svit[0][0] = v0; svit[0][1] = v1;
#pragma unroll 4
        for (int t = 1; t < Sn; t++) {
            float n0 = fmaxf(v0 + t00, v1 + t10) + sem[t][0];
            float n1 = fmaxf(v0 + t01, v1 + t11) + sem[t][1];
            svit[t][0] = n0; svit[t][1] = n1;
            v0 = n0; v1 = n1;
        }
        float f0 = v0 + endt[0];
        float f1 = v1 + endt[1];
        slast = (f1 > f0) ? 1 : 0;
    }

    __syncthreads();

    // backpointer maps: sA[t](tag_t) = tag_{t-1}; sA[0] = identity
    if (tid < 256) {
        if (tid == 0) sA[0] = 2;  // id: f(0)=0, f(1)=1
        int t0 = 2 * tid + 1;
        {
            int c0 = (svit[t0 - 1][1] + t10 > svit[t0 - 1][0] + t00) ? 1 : 0;
            int c1 = (svit[t0 - 1][1] + t11 > svit[t0 - 1][0] + t01) ? 1 : 0;
            sA[t0] = c0 | (c1 << 1);
        }
        int t1 = 2 * tid + 2;
        if (t1 <= Sn - 1) {
            int c0 = (svit[t1 - 1][1] + t10 > svit[t1 - 1][0] + t00) ? 1 : 0;
            int c1 = (svit[t1 - 1][1] + t11 > svit[t1 - 1][0] + t01) ? 1 : 0;
            sA[t1] = c0 | (c1 << 1);
        }
    }
    __syncthreads();

    // suffix composition scan: S[t] = m_t o m_{t+1} o ... o m_{511}
    int* cur = sA;
    int* nxt = sB;
    for (int d = 1; d < Sn; d <<= 1) {
        if (tid < 256) {
            int i0 = tid, i1 = tid + 256;
            int f0v = cur[i0];
            int g0v = (i0 + d < Sn) ? cur[i0 + d] : 2;
            int f1v = cur[i1];
            int g1v = (i1 + d < Sn) ? cur[i1 + d] : 2;
            nxt[i0] = mapcomp(f0v, g0v);
            nxt[i1] = mapcomp(f1v, g1v);
        }
        __syncthreads();
        int* tmp = cur; cur = nxt; nxt = tmp;
    }

    // tags: tag_{511} = last; tag_t = S[t+1](last)
    if (out_size >= 1 + BSn) {
        int last = slast;
        if (tid < 256) {
            int i0 = tid, i1 = tid + 256;
            int tag0 = (i0 == Sn - 1) ? last : ((cur[i0 + 1] >> last) & 1);
            int tag1 = (i1 == Sn - 1) ? last : ((cur[i1 + 1] >> last) & 1);
            out[1 + (size_t)b * Sn + i0] = (float)tag0;
            out[1 + (size_t)b * Sn + i1] = (float)tag1;
        }
    }
}

// ---------------------------------------------------------------------------
extern "C" void kernel_launch(void* const* d_in, const int* in_sizes, int n_in,
                              void* d_out, int out_size)
{
    const float* seq    = (const float*)d_in[0];
    const int*   ids    = (const int*)d_in[1];
    const int*   labels = (const int*)d_in[2];
    const float* W      = (const float*)d_in[3];
    const float* bvec   = (const float*)d_in[4];
    const float* startt = (const float*)d_in[5];
    const float* endt   = (const float*)d_in[6];
    const float* trans  = (const float*)d_in[7];
    float* out = (float*)d_out;

    const int smem = 8 * DEPTH * 192 * 16;  // 98304 B
    cudaFuncSetAttribute(emissions_kernel,
                         cudaFuncAttributeMaxDynamicSharedMemorySize, smem);

    emissions_kernel<<<NBLK, 256, smem>>>(seq, ids, labels, W, bvec, out, out_size);
    crf_kernel<<<Bn, 288>>>(ids, labels, startt, endt, trans, out, out_size);
}

// round 4
// speedup vs baseline: 1.8202x; 1.1722x over previous
#include <cuda_runtime.h>
#include <cstdint>
#include <math.h>

#define Bn 64
#define Sn 512
#define Dn 768
#define BSn (Bn * Sn)

#define PAD_ID 0
#define SEP_ID 103
#define IGNORE_ID 100

#define NBLK 296              // 2 CTAs per SM on 148 SMs
#define NWARP (NBLK * 8)      // 2368 global warps
#define DEPTH 4               // cp.async ring depth per warp

#define NEG_BIG (-1.0e30f)

// Scratch (no cudaMalloc allowed)
__device__ float g_em[BSn * 2];            // emissions (B,S,2)
__device__ unsigned long long g_acc;       // fixed-point llh accumulator
__device__ int g_done;                     // batches finished

// ---------------------------------------------------------------------------
// Kernel 1: em = relu((seq * mask) @ W^T + b); also labels_m and mask outputs.
// Persistent grid, warp-per-token, depth-4 cp.async ring into smem. (R3, proven)
// ---------------------------------------------------------------------------
__global__ __launch_bounds__(256, 2) void emissions_kernel(
    const float* __restrict__ seq,
    const int* __restrict__ ids,
    const int* __restrict__ labels,
    const float* __restrict__ W,
    const float* __restrict__ bvec,
    float* __restrict__ out,
    int out_size)
{
    extern __shared__ float4 sbuf[];   // [8 warps][DEPTH][192 float4]

    const int tid  = threadIdx.x;
    const int warp = tid >> 5;
    const int lane = tid & 31;

    if (blockIdx.x == 0 && tid == 0) { g_acc = 0ULL; g_done = 0; }

    float4 w0[6], w1[6];
    const float4* W4 = reinterpret_cast<const float4*>(W);
#pragma unroll
    for (int k = 0; k < 6; k++) {
        w0[k] = W4[lane + 32 * k];
        w1[k] = W4[192 + lane + 32 * k];
    }
    const float b0 = bvec[0];
    const float b1 = bvec[1];

    const int gw   = blockIdx.x * 8 + warp;
    const int ntok = (BSn - gw + NWARP - 1) / NWARP;

    int myid = 0, mylab = 0;
    if (lane < ntok) {
        int t = gw + lane * NWARP;
        myid  = ids[t];
        mylab = labels[t];
    }

    float4* mybuf = sbuf + (size_t)warp * DEPTH * 192;

    auto issue = [&](int i) {
        if (i < ntok) {
            int t = gw + i * NWARP;
            const float4* g = reinterpret_cast<const float4*>(seq + (size_t)t * Dn) + lane;
            uint32_t sm = (uint32_t)__cvta_generic_to_shared(mybuf + (i & (DEPTH - 1)) * 192 + lane);
#pragma unroll
            for (int k = 0; k < 6; k++) {
                asm volatile("cp.async.cg.shared.global [%0], [%1], 16;\n"
                             :: "r"(sm + k * 32 * 16), "l"(g + k * 32) : "memory");
            }
        }
        asm volatile("cp.async.commit_group;\n" ::: "memory");
    };

    issue(0); issue(1); issue(2); issue(3);

    for (int i = 0; i < ntok; i++) {
        asm volatile("cp.async.wait_group 3;\n" ::: "memory");
        const float4* xb = mybuf + (i & (DEPTH - 1)) * 192;

        float s0 = 0.f, s1 = 0.f;
#pragma unroll
        for (int k = 0; k < 6; k++) {
            float4 x = xb[lane + 32 * k];
            s0 += x.x * w0[k].x + x.y * w0[k].y + x.z * w0[k].z + x.w * w0[k].w;
            s1 += x.x * w1[k].x + x.y * w1[k].y + x.z * w1[k].z + x.w * w1[k].w;
        }

        issue(i + 4);

#pragma unroll
        for (int off = 16; off; off >>= 1) {
            s0 += __shfl_down_sync(0xFFFFFFFFu, s0, off);
            s1 += __shfl_down_sync(0xFFFFFFFFu, s1, off);
        }
        int id_i  = __shfl_sync(0xFFFFFFFFu, myid, i);
        int lab_i = __shfl_sync(0xFFFFFFFFu, mylab, i);

        if (lane == 0) {
            int t = gw + i * NWARP;
            bool m = (id_i != PAD_ID) && (id_i != SEP_ID) && (lab_i != IGNORE_ID);
            float dot0 = m ? s0 : 0.f;
            float dot1 = m ? s1 : 0.f;
            g_em[t * 2 + 0] = fmaxf(dot0 + b0, 0.f);
            g_em[t * 2 + 1] = fmaxf(dot1 + b1, 0.f);
            if (out_size >= 1 + 3 * BSn) {
                out[1 + BSn + t]     = m ? (float)lab_i : 0.f;
                out[1 + 2 * BSn + t] = m ? 1.f : 0.f;
            }
        }
    }
}

// ---------------------------------------------------------------------------
// CRF helpers
// ---------------------------------------------------------------------------
__device__ __forceinline__ float lse2(float a, float b) {
    float m = fmaxf(a, b);
    if (m == -INFINITY) return -INFINITY;
    float n = fminf(a, b);
    return m + log1pf(expf(n - m));
}

__device__ __forceinline__ float4 lsemm(float4 A, float4 B) {
    float4 C;
    C.x = lse2(A.x + B.x, A.y + B.z);
    C.y = lse2(A.x + B.y, A.y + B.w);
    C.z = lse2(A.z + B.x, A.w + B.z);
    C.w = lse2(A.z + B.y, A.w + B.w);
    return C;
}

// max-plus 2x2 matmul, A earlier: C[i][j] = max_k A[i][k] + B[k][j]
__device__ __forceinline__ float4 mpmm(float4 A, float4 B) {
    float4 C;
    C.x = fmaxf(A.x + B.x, A.y + B.z);
    C.y = fmaxf(A.x + B.y, A.y + B.w);
    C.z = fmaxf(A.z + B.x, A.w + B.z);
    C.w = fmaxf(A.z + B.y, A.w + B.w);
    return C;
}

// compose tag maps: (f o g)(x) = f(g(x)); 2-bit encoding, bit x = f(x)
__device__ __forceinline__ int mapcomp(int f, int g) {
    int h0 = (f >> (g & 1)) & 1;
    int h1 = (f >> ((g >> 1) & 1)) & 1;
    return h0 | (h1 << 1);
}

__device__ __forceinline__ float4 shfl_down_f4(float4 v, int off) {
    float4 r;
    r.x = __shfl_down_sync(0xFFFFFFFFu, v.x, off);
    r.y = __shfl_down_sync(0xFFFFFFFFu, v.y, off);
    r.z = __shfl_down_sync(0xFFFFFFFFu, v.z, off);
    r.w = __shfl_down_sync(0xFFFFFFFFu, v.w, off);
    return r;
}

// ---------------------------------------------------------------------------
// CRF kernel: one 256-thread block per batch. Fully parallel:
//  - Viterbi forward via max-plus 2x2 Kogge-Stone prefix scan (9 steps)
//  - backpointers + integer map-composition suffix scan (9 steps, R3-proven)
//  - logZ via ordered warp-shuffle lse 2x2 tree (same association as R3)
//  - gold score via warp shuffles; loss folded in via fixed-point atomic
// ---------------------------------------------------------------------------
__global__ __launch_bounds__(256) void crf_kernel(
    const int* __restrict__ ids,
    const int* __restrict__ labels,
    const float* __restrict__ startt,
    const float* __restrict__ endt,
    const float* __restrict__ trans,
    float* __restrict__ out,
    int out_size)
{
    __shared__ float  sem[Sn][2];
    __shared__ int    stag[Sn];
    __shared__ float4 sPa[Sn];       // max-plus prefix scan ping
    __shared__ float4 sPb[Sn];       // max-plus prefix scan pong
    __shared__ float  salpha[Sn][2]; // viterbi forward scores
    __shared__ int    sA[Sn];
    __shared__ int    sB[Sn];
    __shared__ float4 swmat[8];      // lse per-warp results
    __shared__ float  swsum[8];      // gold per-warp partials
    __shared__ int    slast;

    const int b    = blockIdx.x;
    const int tid  = threadIdx.x;
    const int lane = tid & 31;
    const int warp = tid >> 5;

    // ---- Phase A: loads ----
    const float* emrow = g_em + (size_t)b * Sn * 2;
    for (int i = tid; i < Sn * 2; i += 256)
        reinterpret_cast<float*>(sem)[i] = emrow[i];
    for (int s = tid; s < Sn; s += 256) {
        int id  = ids[(size_t)b * Sn + s];
        int lab = labels[(size_t)b * Sn + s];
        bool m = (id != PAD_ID) && (id != SEP_ID) && (lab != IGNORE_ID);
        stag[s] = m ? lab : 0;
    }
    __syncthreads();

    const float t00 = trans[0], t01 = trans[1], t10 = trans[2], t11 = trans[3];

    // ---- Phase B: gold partial, lse leaf + warp reduce, max-plus leaves ----
    // gold partial (2 tokens/thread)
    float gpart = 0.f;
    {
        int s = tid;
        int a = stag[s];
        gpart += sem[s][a];
        int c = stag[s + 1];
        gpart += (a == 0) ? (c == 0 ? t00 : t01) : (c == 0 ? t10 : t11);
        s = tid + 256;
        a = stag[s];
        gpart += sem[s][a];
        if (s < Sn - 1) {
            c = stag[s + 1];
            gpart += (a == 0) ? (c == 0 ? t00 : t01) : (c == 0 ? t10 : t11);
        }
    }
#pragma unroll
    for (int off = 16; off; off >>= 1)
        gpart += __shfl_down_sync(0xFFFFFFFFu, gpart, off);
    if (lane == 0) swsum[warp] = gpart;

    // lse leaf: combine t = 2*tid+1, 2*tid+2 (same leaves as R3)
    {
        int t0 = 2 * tid + 1;
        float4 Mv;
        float e0 = sem[t0][0], e1 = sem[t0][1];
        Mv.x = t00 + e0; Mv.y = t01 + e1;
        Mv.z = t10 + e0; Mv.w = t11 + e1;
        int t1 = 2 * tid + 2;
        if (t1 <= Sn - 1) {
            float4 Mb;
            e0 = sem[t1][0]; e1 = sem[t1][1];
            Mb.x = t00 + e0; Mb.y = t01 + e1;
            Mb.z = t10 + e0; Mb.w = t11 + e1;
            Mv = lsemm(Mv, Mb);
        }
        // ordered warp tree (adjacent pairing, same association as R3 tree)
#pragma unroll
        for (int off = 1; off <= 16; off <<= 1) {
            float4 o = shfl_down_f4(Mv, off);
            Mv = lsemm(Mv, o);
        }
        if (lane == 0) swmat[warp] = Mv;
    }

    // max-plus leaves: index 0 = identity, index t>=1 = M_t
    {
        float4 I; I.x = 0.f; I.y = NEG_BIG; I.z = NEG_BIG; I.w = 0.f;
        int i1 = tid;
        if (i1 == 0) {
            sPa[0] = I;
        } else {
            float e0 = sem[i1][0], e1 = sem[i1][1];
            float4 M; M.x = t00 + e0; M.y = t01 + e1; M.z = t10 + e0; M.w = t11 + e1;
            sPa[i1] = M;
        }
        int i2 = tid + 256;
        float e0 = sem[i2][0], e1 = sem[i2][1];
        float4 M; M.x = t00 + e0; M.y = t01 + e1; M.z = t10 + e0; M.w = t11 + e1;
        sPa[i2] = M;
    }
    __syncthreads();

    // ---- Phase C: logZ final + loss (warp 0) runs alongside KS scan start ----
    if (warp == 0) {
        float4 m;
        if (lane < 8) m = swmat[lane];
        else { m.x = 0.f; m.y = NEG_BIG; m.z = NEG_BIG; m.w = 0.f; }
        float gs = (lane < 8) ? swsum[lane] : 0.f;
#pragma unroll
        for (int off = 1; off <= 4; off <<= 1) {
            float4 o = shfl_down_f4(m, off);
            m = lsemm(m, o);
            gs += __shfl_down_sync(0xFFFFFFFFu, gs, off);
        }
        if (lane == 0) {
            float score = gs + startt[stag[0]] + endt[stag[Sn - 1]];
            float a0 = startt[0] + sem[0][0];
            float a1 = startt[1] + sem[0][1];
            float f0 = lse2(a0 + m.x, a1 + m.z);
            float f1 = lse2(a0 + m.y, a1 + m.w);
            float logZ = lse2(f0 + endt[0], f1 + endt[1]);
            float llh = score - logZ;
            long long fx = __double2ll_rn((double)llh * 4294967296.0);
            atomicAdd(&g_acc, (unsigned long long)fx);
            __threadfence();
            int old = atomicAdd(&g_done, 1);
            if (old == Bn - 1) {
                __threadfence();
                unsigned long long a = atomicAdd(&g_acc, 0ULL);
                double s = (double)(long long)a * (1.0 / 4294967296.0);
                out[0] = (float)(s / (double)BSn);
            }
        }
    }

    // ---- Phase D: max-plus Kogge-Stone prefix scan, 9 steps ----
    float4* cur = sPa;
    float4* nxt = sPb;
#pragma unroll
    for (int d = 1; d < Sn; d <<= 1) {
        int i1 = tid, i2 = tid + 256;
        float4 v1 = cur[i1];
        if (i1 >= d) v1 = mpmm(cur[i1 - d], v1);
        float4 v2 = mpmm(cur[i2 - d], cur[i2]);   // i2 >= 256 >= d always
        nxt[i1] = v1;
        nxt[i2] = v2;
        __syncthreads();
        float4* tmp = cur; cur = nxt; nxt = tmp;
    }

    // ---- Phase E: alpha from prefix products ----
    {
        float a0 = startt[0] + sem[0][0];
        float a1 = startt[1] + sem[0][1];
        int i1 = tid;
        if (i1 == 0) {
            salpha[0][0] = a0; salpha[0][1] = a1;
        } else {
            float4 P = cur[i1];
            salpha[i1][0] = fmaxf(a0 + P.x, a1 + P.z);
            salpha[i1][1] = fmaxf(a0 + P.y, a1 + P.w);
        }
        int i2 = tid + 256;
        float4 P = cur[i2];
        salpha[i2][0] = fmaxf(a0 + P.x, a1 + P.z);
        salpha[i2][1] = fmaxf(a0 + P.y, a1 + P.w);
    }
    __syncthreads();

    // ---- Phase F: backpointer maps + last tag ----
    {
        int t = tid;
        if (t == 0) {
            sA[0] = 2;  // identity map
        } else {
            int c0 = (salpha[t - 1][1] + t10 > salpha[t - 1][0] + t00) ? 1 : 0;
            int c1 = (salpha[t - 1][1] + t11 > salpha[t - 1][0] + t01) ? 1 : 0;
            sA[t] = c0 | (c1 << 1);
        }
        t = tid + 256;
        int c0 = (salpha[t - 1][1] + t10 > salpha[t - 1][0] + t00) ? 1 : 0;
        int c1 = (salpha[t - 1][1] + t11 > salpha[t - 1][0] + t01) ? 1 : 0;
        sA[t] = c0 | (c1 << 1);
        if (tid == 255) {
            float f0 = salpha[Sn - 1][0] + endt[0];
            float f1 = salpha[Sn - 1][1] + endt[1];
            slast = (f1 > f0) ? 1 : 0;
        }
    }
    __syncthreads();

    // ---- Phase G: suffix map-composition scan (R3-proven), 9 steps ----
    int* mcur = sA;
    int* mnxt = sB;
#pragma unroll
    for (int d = 1; d < Sn; d <<= 1) {
        int i0 = tid, i1 = tid + 256;
        int f0v = mcur[i0];
        int g0v = (i0 + d < Sn) ? mcur[i0 + d] : 2;
        int f1v = mcur[i1];
        int g1v = (i1 + d < Sn) ? mcur[i1 + d] : 2;
        mnxt[i0] = mapcomp(f0v, g0v);
        mnxt[i1] = mapcomp(f1v, g1v);
        __syncthreads();
        int* tmp = mcur; mcur = mnxt; mnxt = tmp;
    }

    // ---- Phase H: write tags ----
    if (out_size >= 1 + BSn) {
        int last = slast;
        int i0 = tid, i1 = tid + 256;
        int tag0 = (mcur[i0 + 1] >> last) & 1;            // i0 <= 255 < 511
        int tag1 = (i1 == Sn - 1) ? last : ((mcur[i1 + 1] >> last) & 1);
        out[1 + (size_t)b * Sn + i0] = (float)tag0;
        out[1 + (size_t)b * Sn + i1] = (float)tag1;
    }
}

// ---------------------------------------------------------------------------
extern "C" void kernel_launch(void* const* d_in, const int* in_sizes, int n_in,
                              void* d_out, int out_size)
{
    const float* seq    = (const float*)d_in[0];
    const int*   ids    = (const int*)d_in[1];
    const int*   labels = (const int*)d_in[2];
    const float* W      = (const float*)d_in[3];
    const float* bvec   = (const float*)d_in[4];
    const float* startt = (const float*)d_in[5];
    const float* endt   = (const float*)d_in[6];
    const float* trans  = (const float*)d_in[7];
    float* out = (float*)d_out;

    const int smem = 8 * DEPTH * 192 * 16;  // 98304 B
    cudaFuncSetAttribute(emissions_kernel,
                         cudaFuncAttributeMaxDynamicSharedMemorySize, smem);

    emissions_kernel<<<NBLK, 256, smem>>>(seq, ids, labels, W, bvec, out, out_size);
    crf_kernel<<<Bn, 256>>>(ids, labels, startt, endt, trans, out, out_size);
}